// round 17
// baseline (speedup 1.0000x reference)
#include <cuda_runtime.h>
#include <cstdint>

#define Cc 64
#define CO 64
#define Ss 256
#define LL (Ss * Ss)

#define CHUNK 4               // channels per pipeline chunk
#define NCHUNK (Cc / CHUNK)   // 16 chunks

// ---------------------------------------------------------------------------
// Depth-2 register-staged pipelined fused Reverb kernel.
//   g[c,l]   = x[c,l] * sum_{i,j valid} w[c*9+i*3+j, (y+1-i)*S + (x+1-j)]
//   out[o,l] = sum_c conv[c,o] * g[c,l]
// Block owns 128 px. Task = (channel, 2px); staging is float2 so TWO chunk
// buffers fit in registers -> loads for chunks s+1 AND s+2 are in flight
// simultaneously (DRAM queue never drains). Boundary taps via warp
// shuffles; lanes 0/31 carry predicated scalar loads.
// ---------------------------------------------------------------------------
__global__ __launch_bounds__(256, 2) void reverb_pipe2_kernel(
    const float* __restrict__ x,      // (C, L)
    const float* __restrict__ w,      // (C*9, L)
    const float* __restrict__ conv,   // (C, CO)
    float* __restrict__ out)          // (CO, L)
{
    __shared__ __align__(16) float sconv[Cc * CO];        // 16 KB
    __shared__ __align__(16) float sg[2][CHUNK * 128];    // 4 KB

    const int tid = threadIdx.x;
    const int wid = tid >> 5;
    const int lane = tid & 31;

    // conv table (first consumer use is after the first __syncthreads)
#pragma unroll
    for (int k = 0; k < 4; k++) {
        const int i = tid + 256 * k;
        ((float4*)sconv)[i] = ((const float4*)conv)[i];
    }

    const int lbase = blockIdx.x * 128;
    const int yb = lbase >> 8;
    const int xb = lbase & 255;

    // Task geometry: channel slot + 2-px group
    const int cl = tid >> 6;          // 0..3
    const int grp = tid & 63;         // 0..63
    const int x0 = xb + grp * 2;

    const bool edgeL = (lane == 0) && (x0 != 0);
    const bool edgeR = (lane == 31) && (x0 != Ss - 2);

    float my[3];
    int rowoff[3];
#pragma unroll
    for (int i = 0; i < 3; i++) {
        const int ry = yb + 1 - i;
        const bool vy = (unsigned)ry < (unsigned)Ss;
        my[i] = vy ? 1.0f : 0.0f;
        rowoff[i] = (vy ? ry : yb) * Ss + x0;
    }

    // TWO front-batched staging buffers (float2): 9 planes + x + edges each
    float2 a[2][3], b[2][3], d[2][3], xv[2];
    float le[2][3], re[2][3];

    auto LOAD = [&](int s, int p) {
        const int c = s * CHUNK + cl;
        const float* wc = w + (size_t)c * 9 * LL;
#pragma unroll
        for (int i = 0; i < 3; i++) {
            const float* p0 = wc + (size_t)(i * 3 + 0) * LL + rowoff[i];
            const float* p1 = wc + (size_t)(i * 3 + 1) * LL + rowoff[i];
            const float* p2 = wc + (size_t)(i * 3 + 2) * LL + rowoff[i];
            a[p][i] = __ldg((const float2*)p0);
            b[p][i] = __ldg((const float2*)p1);
            d[p][i] = __ldg((const float2*)p2);
            le[p][i] = edgeL ? __ldg(p2 - 1) : 0.0f;
            re[p][i] = edgeR ? __ldg(p0 + 2) : 0.0f;
        }
        xv[p] = __ldg((const float2*)(x + (size_t)c * LL + lbase + grp * 2));
    };

    unsigned long long acc[4][4];     // [o-pair][pixel]
#pragma unroll
    for (int op = 0; op < 4; op++)
#pragma unroll
        for (int p = 0; p < 4; p++) acc[op][p] = 0ull;

    LOAD(0, 0);
    LOAD(1, 1);

    const int og = wid;               // warp owns outputs [8og, 8og+8)

    for (int s = 0; s < NCHUNK; s++) {
        const int p = s & 1;

        // ---- g for my (channel, 2px) task from staging buffer p ----
        float ws0 = 0.f, ws1 = 0.f;
#pragma unroll
        for (int i = 0; i < 3; i++) {
            // left tap for px0 (plane j2 @ x0-1): prev lane's d.y
            float lsv = __shfl_up_sync(0xffffffffu, d[p][i].y, 1);
            if (lane == 0) lsv = le[p][i];
            // right tap for px1 (plane j0 @ x0+2): next lane's a.x
            float rsv = __shfl_down_sync(0xffffffffu, a[p][i].x, 1);
            if (lane == 31) rsv = re[p][i];

            ws0 = fmaf(my[i], (a[p][i].y + b[p][i].x) + lsv, ws0);
            ws1 = fmaf(my[i], (rsv + b[p][i].y) + d[p][i].x, ws1);
        }
        float2 gv;
        gv.x = xv[p].x * ws0;
        gv.y = xv[p].y * ws1;
        *(float2*)(&sg[p][cl * 128 + grp * 2]) = gv;

        // Buffer p just consumed -> refill with chunk s+2 (depth-2 pipe).
        if (s + 2 < NCHUNK) LOAD(s + 2, p);

        __syncthreads();   // chunk s staged (also orders sconv on s==0)

        // ---- mix chunk s from smem (4 channels) ----
        const float* src = sg[p];
#pragma unroll
        for (int c2 = 0; c2 < CHUNK; c2++) {
            const int c = s * CHUNK + c2;
            const float4 g4 = *(const float4*)(src + c2 * 128 + lane * 4);
            unsigned long long gp[4];
            asm("mov.b64 %0, {%1, %1};" : "=l"(gp[0]) : "f"(g4.x));
            asm("mov.b64 %0, {%1, %1};" : "=l"(gp[1]) : "f"(g4.y));
            asm("mov.b64 %0, {%1, %1};" : "=l"(gp[2]) : "f"(g4.z));
            asm("mov.b64 %0, {%1, %1};" : "=l"(gp[3]) : "f"(g4.w));

            const ulonglong2* cv = (const ulonglong2*)(sconv + c * CO + og * 8);
            const ulonglong2 cva = cv[0];
            const ulonglong2 cvb = cv[1];
#pragma unroll
            for (int q = 0; q < 4; q++) {
                asm("fma.rn.f32x2 %0, %1, %2, %0;" : "+l"(acc[0][q]) : "l"(cva.x), "l"(gp[q]));
                asm("fma.rn.f32x2 %0, %1, %2, %0;" : "+l"(acc[1][q]) : "l"(cva.y), "l"(gp[q]));
                asm("fma.rn.f32x2 %0, %1, %2, %0;" : "+l"(acc[2][q]) : "l"(cvb.x), "l"(gp[q]));
                asm("fma.rn.f32x2 %0, %1, %2, %0;" : "+l"(acc[3][q]) : "l"(cvb.y), "l"(gp[q]));
            }
        }
        // sg double buffer: STS(s+1) targets sg[1-p]; re-write of sg[p]
        // happens at s+2, after the s+1 barrier has retired all mix(s) readers.
    }

    // ---- Epilogue: unpack, 8 coalesced STG.128 per warp ----
#pragma unroll
    for (int op = 0; op < 4; op++) {
        unsigned int lo[4], hi[4];
#pragma unroll
        for (int q = 0; q < 4; q++) {
            asm("mov.b64 {%0, %1}, %2;" : "=r"(lo[q]), "=r"(hi[q]) : "l"(acc[op][q]));
        }
        const int o = og * 8 + 2 * op;
        float4 v0, v1;
        v0.x = __uint_as_float(lo[0]); v0.y = __uint_as_float(lo[1]);
        v0.z = __uint_as_float(lo[2]); v0.w = __uint_as_float(lo[3]);
        v1.x = __uint_as_float(hi[0]); v1.y = __uint_as_float(hi[1]);
        v1.z = __uint_as_float(hi[2]); v1.w = __uint_as_float(hi[3]);
        *(float4*)(out + (size_t)o * LL + lbase + lane * 4) = v0;
        *(float4*)(out + (size_t)(o + 1) * LL + lbase + lane * 4) = v1;
    }
}

extern "C" void kernel_launch(void* const* d_in, const int* in_sizes, int n_in,
                              void* d_out, int out_size) {
    const float* x    = (const float*)d_in[0];  // (1, C, S, S)
    const float* w    = (const float*)d_in[1];  // (1, C*9, L)
    const float* conv = (const float*)d_in[2];  // (C, CO)
    float* out = (float*)d_out;                 // (1, CO, S, S)

    reverb_pipe2_kernel<<<LL / 128, 256>>>(x, w, conv, out);
}